// round 1
// baseline (speedup 1.0000x reference)
#include <cuda_runtime.h>

// Residual quantization: N=65536 vectors, D=128 dims, M=8 stages, K=256 codewords.
// Output layout (float32): [ x_recon (N*D) | codes one-hot (N*M*K) | side_output (M*N*D) ]
//
// Strategy: one thread per vector, residual held in registers as packed f32x2.
// Per stage: codebook (128KB) staged into padded smem; distances via warp-uniform
// broadcast LDS.128 feeding packed fma.rn.f32x2 (Blackwell FFMA2, 2x fp32 rate).
// All outputs (incl. zero-fill of one-hot codes) written in the per-stage epilogue.

#define NV 65536
#define DD 128
#define MS 8
#define KC 256
#define ROWF 132                      // padded codebook row stride (floats): kills gather conflicts
#define SMEM_FLOATS (KC * ROWF + KC)  // codebook + cnorm
#define SMEM_BYTES (SMEM_FLOATS * 4)

typedef unsigned long long u64;

__device__ __forceinline__ u64 pk2(float lo, float hi) {
    u64 r;
    asm("mov.b64 %0, {%1, %2};" : "=l"(r) : "f"(lo), "f"(hi));
    return r;
}
__device__ __forceinline__ void upk2(u64 v, float& lo, float& hi) {
    asm("mov.b64 {%0, %1}, %2;" : "=f"(lo), "=f"(hi) : "l"(v));
}
// Packed dual-fp32 FMA (Blackwell FFMA2). Only reachable via PTX fma.rn.f32x2.
__device__ __forceinline__ void ffma2(u64& d, u64 a, u64 b) {
    asm("fma.rn.f32x2 %0, %1, %2, %0;" : "+l"(d) : "l"(a), "l"(b));
}

__global__ void __launch_bounds__(256, 1)
rq_kernel(const float* __restrict__ x, const float* __restrict__ cb,
          float* __restrict__ out_recon, float* __restrict__ out_codes,
          float* __restrict__ out_side)
{
    extern __shared__ float sm[];
    float* sC = sm;               // [KC][ROWF] padded codebook
    float* sN = sm + KC * ROWF;   // [KC] codeword squared norms

    const int tid = threadIdx.x;
    const int n = blockIdx.x * 256 + tid;   // grid is exactly 256 blocks * 256 threads

    // Load this vector (initial residual) into registers as 64 packed f32x2.
    u64 r2[DD / 2];
    {
        const ulonglong2* xr = (const ulonglong2*)(x + (size_t)n * DD);
        #pragma unroll
        for (int j4 = 0; j4 < DD / 4; ++j4) {
            ulonglong2 v = xr[j4];
            r2[2 * j4]     = v.x;
            r2[2 * j4 + 1] = v.y;
        }
    }

    for (int m = 0; m < MS; ++m) {
        __syncthreads();  // previous stage done reading sC
        // ---- stage codebook into padded smem (coalesced) ----
        {
            const float4* src = (const float4*)(cb + (size_t)m * KC * DD);
            for (int i = tid; i < KC * (DD / 4); i += 256) {
                int k = i >> 5, j4 = i & 31;
                *((float4*)(sC + k * ROWF + 4 * j4)) = src[i];
            }
        }
        __syncthreads();
        // ---- codeword squared norms (thread t -> codeword t) ----
        {
            const float4* row = (const float4*)(sC + tid * ROWF);
            float s = 0.f;
            #pragma unroll
            for (int j4 = 0; j4 < 32; ++j4) {
                float4 v = row[j4];
                s = fmaf(v.x, v.x, s); s = fmaf(v.y, v.y, s);
                s = fmaf(v.z, v.z, s); s = fmaf(v.w, v.w, s);
            }
            sN[tid] = s;
        }
        __syncthreads();

        // ---- distances: d2[k] = cnorm[k] - 2 * <r, c_k>   (||r||^2 constant per row) ----
        float best = 3.4e38f;
        int bestk = 0;
        #pragma unroll 1
        for (int k0 = 0; k0 < KC; k0 += 8) {
            u64 acc[8];
            #pragma unroll
            for (int kk = 0; kk < 8; ++kk) acc[kk] = 0ull;

            const char* base = (const char*)(sC + k0 * ROWF);
            #pragma unroll
            for (int j4 = 0; j4 < 32; ++j4) {
                #pragma unroll
                for (int kk = 0; kk < 8; ++kk) {
                    // 16B broadcast load = two packed f32x2 codebook pairs
                    ulonglong2 cc = *((const ulonglong2*)(base + kk * (ROWF * 4) + 16 * j4));
                    ffma2(acc[kk], r2[2 * j4],     cc.x);
                    ffma2(acc[kk], r2[2 * j4 + 1], cc.y);
                }
            }
            #pragma unroll
            for (int kk = 0; kk < 8; ++kk) {
                float a, b;
                upk2(acc[kk], a, b);
                float d2v = fmaf(-2.0f, a + b, sN[k0 + kk]);
                if (d2v < best) { best = d2v; bestk = k0 + kk; }  // first-min tie rule (argmin)
            }
        }

        // ---- residual update + side_output (+ final recon) ----
        {
            const float* crow = sC + bestk * ROWF;   // per-thread gather; padding avoids conflicts
            const float4* xr = (const float4*)(x + (size_t)n * DD);
            float4* sd = (float4*)(out_side + ((size_t)m * NV + n) * DD);
            float4* rc = (float4*)(out_recon + (size_t)n * DD);
            #pragma unroll
            for (int j4 = 0; j4 < 32; ++j4) {
                float4 c4 = *((const float4*)(crow + 4 * j4));
                float a0, a1, b0, b1;
                upk2(r2[2 * j4], a0, a1);
                upk2(r2[2 * j4 + 1], b0, b1);
                a0 -= c4.x; a1 -= c4.y; b0 -= c4.z; b1 -= c4.w;
                r2[2 * j4]     = pk2(a0, a1);
                r2[2 * j4 + 1] = pk2(b0, b1);
                float4 xv = xr[j4];
                float4 s4 = make_float4(xv.x - a0, xv.y - a1, xv.z - b0, xv.w - b1);
                sd[j4] = s4;                     // x_recon after stage m
                if (m == MS - 1) rc[j4] = s4;    // final x_recon
            }
        }
        // ---- one-hot codes row (also performs the zero-fill, overlapped with compute) ----
        {
            float4* cd = (float4*)(out_codes + (size_t)n * (MS * KC) + (size_t)m * KC);
            int q = bestk >> 2, rsel = bestk & 3;
            #pragma unroll 8
            for (int t = 0; t < KC / 4; ++t) {
                float4 v = make_float4(0.f, 0.f, 0.f, 0.f);
                if (t == q) {
                    if      (rsel == 0) v.x = 1.f;
                    else if (rsel == 1) v.y = 1.f;
                    else if (rsel == 2) v.z = 1.f;
                    else                v.w = 1.f;
                }
                cd[t] = v;
            }
        }
    }
}

extern "C" void kernel_launch(void* const* d_in, const int* in_sizes, int n_in,
                              void* d_out, int out_size)
{
    const float* x  = (const float*)d_in[0];   // (N, D) fp32
    const float* cb = (const float*)d_in[1];   // (M, K, D) fp32

    float* out       = (float*)d_out;
    float* out_recon = out;                                        // N*D
    float* out_codes = out + (size_t)NV * DD;                      // N*M*K
    float* out_side  = out_codes + (size_t)NV * MS * KC;           // M*N*D

    cudaFuncSetAttribute(rq_kernel, cudaFuncAttributeMaxDynamicSharedMemorySize, SMEM_BYTES);
    rq_kernel<<<NV / 256, 256, SMEM_BYTES>>>(x, cb, out_recon, out_codes, out_side);
}